// round 2
// baseline (speedup 1.0000x reference)
#include <cuda_runtime.h>
#include <cuda_bf16.h>

#define D 64
#define TILE_M 128
#define NTHREADS 256
#define STAGE_STRIDE 130   // even (keeps 8B alignment for f32x2 loads), de-conflicts transpose
#define NREP 64
#define MAX_N 100000

// ---------------- scratch (device globals; no allocations allowed) ----------------
__device__ float g_neigh[MAX_N * D];
__device__ float g_sum[2][NREP][D];
__device__ float g_sq[2][NREP][D];
__device__ __align__(16) float g_mean[2][D];
__device__ __align__(16) float g_rstd[2][D];

// ---------------- packed fp32x2 helpers (Blackwell) ----------------
__device__ __forceinline__ unsigned long long pack2(float lo, float hi) {
    unsigned long long r;
    asm("mov.b64 %0, {%1, %2};" : "=l"(r) : "f"(lo), "f"(hi));
    return r;
}
__device__ __forceinline__ void unpack2(unsigned long long v, float& lo, float& hi) {
    asm("mov.b64 {%0, %1}, %2;" : "=f"(lo), "=f"(hi) : "l"(v));
}
__device__ __forceinline__ unsigned long long fma2(unsigned long long a,
                                                   unsigned long long b,
                                                   unsigned long long c) {
    unsigned long long d;
    asm("fma.rn.f32x2 %0, %1, %2, %3;" : "=l"(d) : "l"(a), "l"(b), "l"(c));
    return d;
}

// ---------------- K0: zero scratch ----------------
__global__ void zero_kernel() {
    int tid = blockIdx.x * blockDim.x + threadIdx.x;
    int stride = gridDim.x * blockDim.x;
    float4* p = (float4*)g_neigh;
    const int n4 = MAX_N * D / 4;
    for (int i = tid; i < n4; i += stride) p[i] = make_float4(0.f, 0.f, 0.f, 0.f);
    float* s = &g_sum[0][0][0];
    float* q = &g_sq[0][0][0];
    const int ns = 2 * NREP * D;
    for (int i = tid; i < ns; i += stride) { s[i] = 0.f; q[i] = 0.f; }
}

// ---------------- K1: scatter-sum  neigh[dst] += h[src]  ----------------
__global__ void scatter_kernel(const float* __restrict__ h,
                               const int* __restrict__ src,
                               const int* __restrict__ dst, int E) {
    int idx = blockIdx.x * blockDim.x + threadIdx.x;
    int total = E * 16;
    if (idx >= total) return;
    int e = idx >> 4;
    int c = idx & 15;
    int s = __ldg(&src[e]);
    int d = __ldg(&dst[e]);
    float4 v = __ldg((const float4*)(h + (size_t)s * D) + c);
    float* p = g_neigh + (size_t)d * D + c * 4;
    asm volatile("red.global.add.v4.f32 [%0], {%1, %2, %3, %4};"
                 :: "l"(p), "f"(v.x), "f"(v.y), "f"(v.z), "f"(v.w) : "memory");
}

// ---------------- MLP GEMM layer: acc[4 row-pairs][4 cols], k-major operands ----------------
__device__ __forceinline__ void gemm_layer(const float* __restrict__ stageT,
                                           const unsigned long long* __restrict__ Wd,
                                           const float* __restrict__ bias,
                                           int r0, int c0,
                                           unsigned long long acc[4][4]) {
#pragma unroll
    for (int j = 0; j < 4; ++j) {
        float bv = __ldg(&bias[c0 + j]);
        unsigned long long bp = pack2(bv, bv);
#pragma unroll
        for (int p = 0; p < 4; ++p) acc[p][j] = bp;
    }
#pragma unroll 8
    for (int k = 0; k < D; ++k) {
        const float* xr = stageT + k * STAGE_STRIDE + r0;
        unsigned long long x0 = *(const unsigned long long*)(xr + 0);
        unsigned long long x1 = *(const unsigned long long*)(xr + 2);
        unsigned long long x2 = *(const unsigned long long*)(xr + 4);
        unsigned long long x3 = *(const unsigned long long*)(xr + 6);
        ulonglong2 wa = *(const ulonglong2*)(Wd + k * D + c0);
        ulonglong2 wb = *(const ulonglong2*)(Wd + k * D + c0 + 2);
        acc[0][0] = fma2(x0, wa.x, acc[0][0]);
        acc[1][0] = fma2(x1, wa.x, acc[1][0]);
        acc[2][0] = fma2(x2, wa.x, acc[2][0]);
        acc[3][0] = fma2(x3, wa.x, acc[3][0]);
        acc[0][1] = fma2(x0, wa.y, acc[0][1]);
        acc[1][1] = fma2(x1, wa.y, acc[1][1]);
        acc[2][1] = fma2(x2, wa.y, acc[2][1]);
        acc[3][1] = fma2(x3, wa.y, acc[3][1]);
        acc[0][2] = fma2(x0, wb.x, acc[0][2]);
        acc[1][2] = fma2(x1, wb.x, acc[1][2]);
        acc[2][2] = fma2(x2, wb.x, acc[2][2]);
        acc[3][2] = fma2(x3, wb.x, acc[3][2]);
        acc[0][3] = fma2(x0, wb.y, acc[0][3]);
        acc[1][3] = fma2(x1, wb.y, acc[1][3]);
        acc[2][3] = fma2(x2, wb.y, acc[2][3]);
        acc[3][3] = fma2(x3, wb.y, acc[3][3]);
    }
}

// smem: stage[64][STAGE_STRIDE] floats, W1d[4096] u64, W2d[4096] u64, sstat[64], ssq[64]
#define SMEM_BYTES ((64 * STAGE_STRIDE + 2 * 4096 * 2 + 128) * 4)

// ---------------- K2/K3: fused MLP (+ column stats), target 0=nodes 1=edges ----------------
__global__ __launch_bounds__(NTHREADS, 2)
void mlp_kernel(const float* __restrict__ xin,      // nodes: h ; edges: e
                const float* __restrict__ epsp,
                const float* __restrict__ W1, const float* __restrict__ b1,
                const float* __restrict__ W2, const float* __restrict__ b2,
                float* __restrict__ out, int M, int target) {
    extern __shared__ float smem_raw[];
    float* stage = smem_raw;
    unsigned long long* W1d = (unsigned long long*)(smem_raw + 64 * STAGE_STRIDE);
    unsigned long long* W2d = W1d + 4096;
    float* sstat = (float*)(W2d + 4096);
    float* ssq = sstat + 64;

    int tid = threadIdx.x;
    int row0 = blockIdx.x * TILE_M;

    // load + duplicate weights into smem
    for (int i = tid; i < 4096; i += NTHREADS) {
        float w1 = __ldg(&W1[i]);
        float w2 = __ldg(&W2[i]);
        W1d[i] = pack2(w1, w1);
        W2d[i] = pack2(w2, w2);
    }
    if (tid < 64) { sstat[tid] = 0.f; ssq[tid] = 0.f; }

    // load x tile, transposed to k-major (stage[k][r])
    float epsv = 1.f;
    if (target == 0) epsv = 1.f + __ldg(&epsp[0]);
    for (int ch = tid; ch < TILE_M * 16; ch += NTHREADS) {
        int r = ch >> 4;
        int c4 = ch & 15;
        int gr = row0 + r;
        float4 v = make_float4(0.f, 0.f, 0.f, 0.f);
        if (gr < M) {
            if (target == 0) {
                float4 a = __ldg((const float4*)(xin + (size_t)gr * D) + c4);
                float4 n = *((const float4*)(g_neigh + (size_t)gr * D) + c4);
                v.x = fmaf(epsv, a.x, n.x);
                v.y = fmaf(epsv, a.y, n.y);
                v.z = fmaf(epsv, a.z, n.z);
                v.w = fmaf(epsv, a.w, n.w);
            } else {
                v = __ldg((const float4*)(xin + (size_t)gr * D) + c4);
            }
        }
        int c = c4 * 4;
        stage[(c + 0) * STAGE_STRIDE + r] = v.x;
        stage[(c + 1) * STAGE_STRIDE + r] = v.y;
        stage[(c + 2) * STAGE_STRIDE + r] = v.z;
        stage[(c + 3) * STAGE_STRIDE + r] = v.w;
    }
    __syncthreads();

    int tx = tid & 15;
    int ty = tid >> 4;
    int c0 = tx * 4;
    int r0 = ty * 8;

    unsigned long long acc[4][4];
    gemm_layer(stage, W1d, b1, r0, c0, acc);
    __syncthreads();   // all reads of stage (x) done

    // relu + write intermediate t back into stage (k-major: stage[c][r])
#pragma unroll
    for (int j = 0; j < 4; ++j) {
#pragma unroll
        for (int p = 0; p < 4; ++p) {
            float a, b;
            unpack2(acc[p][j], a, b);
            float2 v = make_float2(fmaxf(a, 0.f), fmaxf(b, 0.f));
            *(float2*)(stage + (c0 + j) * STAGE_STRIDE + r0 + 2 * p) = v;
        }
    }
    __syncthreads();

    gemm_layer(stage, W2d, b2, r0, c0, acc);

    // epilogue: store pre-norm y, accumulate column stats
    float cs[4] = {0.f, 0.f, 0.f, 0.f};
    float cq[4] = {0.f, 0.f, 0.f, 0.f};
#pragma unroll
    for (int p = 0; p < 4; ++p) {
        float ya[4], yb[4];
#pragma unroll
        for (int j = 0; j < 4; ++j) unpack2(acc[p][j], ya[j], yb[j]);
        int gr0 = row0 + r0 + 2 * p;
        int gr1 = gr0 + 1;
        if (gr0 < M) {
            *(float4*)(out + (size_t)gr0 * D + c0) = make_float4(ya[0], ya[1], ya[2], ya[3]);
#pragma unroll
            for (int j = 0; j < 4; ++j) { cs[j] += ya[j]; cq[j] += ya[j] * ya[j]; }
        }
        if (gr1 < M) {
            *(float4*)(out + (size_t)gr1 * D + c0) = make_float4(yb[0], yb[1], yb[2], yb[3]);
#pragma unroll
            for (int j = 0; j < 4; ++j) { cs[j] += yb[j]; cq[j] += yb[j] * yb[j]; }
        }
    }
#pragma unroll
    for (int j = 0; j < 4; ++j) {
        atomicAdd(&sstat[c0 + j], cs[j]);
        atomicAdd(&ssq[c0 + j], cq[j]);
    }
    __syncthreads();
    if (tid < 64) {
        int rep = blockIdx.x & (NREP - 1);
        atomicAdd(&g_sum[target][rep][tid], sstat[tid]);
        atomicAdd(&g_sq[target][rep][tid], ssq[tid]);
    }
}

// ---------------- K4: finalize mean / rstd ----------------
__global__ void stats_kernel(int N, int E) {
    int t = threadIdx.x;          // 128 threads
    int target = t >> 6;
    int c = t & 63;
    float s = 0.f, q = 0.f;
#pragma unroll
    for (int r = 0; r < NREP; ++r) { s += g_sum[target][r][c]; q += g_sq[target][r][c]; }
    float cnt = target ? (float)E : (float)N;
    float m = s / cnt;
    float var = q / cnt - m * m;
    g_mean[target][c] = m;
    g_rstd[target][c] = rsqrtf(var + 1e-5f);
}

// ---------------- K5/K6: normalize + relu + residual (in place on d_out) ----------------
__global__ void apply_kernel(const float* __restrict__ res,
                             const float* __restrict__ gamma,
                             const float* __restrict__ beta,
                             float* __restrict__ y, int M, int target) {
    int idx = blockIdx.x * blockDim.x + threadIdx.x;
    int total = M * 16;
    if (idx >= total) return;
    int r = idx >> 4;
    int c4 = idx & 15;
    size_t off = (size_t)r * D + c4 * 4;
    float4 v = *(float4*)(y + off);
    float4 rs = __ldg((const float4*)res + (off >> 2));
    float4 g = __ldg((const float4*)gamma + c4);
    float4 b = __ldg((const float4*)beta + c4);
    int c = c4 * 4;
    float4 m = *(const float4*)&g_mean[target][c];
    float4 sd = *(const float4*)&g_rstd[target][c];
    float4 o;
    o.x = rs.x + fmaxf(g.x * (v.x - m.x) * sd.x + b.x, 0.f);
    o.y = rs.y + fmaxf(g.y * (v.y - m.y) * sd.y + b.y, 0.f);
    o.z = rs.z + fmaxf(g.z * (v.z - m.z) * sd.z + b.z, 0.f);
    o.w = rs.w + fmaxf(g.w * (v.w - m.w) * sd.w + b.w, 0.f);
    *(float4*)(y + off) = o;
}

// ---------------- launcher ----------------
extern "C" void kernel_launch(void* const* d_in, const int* in_sizes, int n_in,
                              void* d_out, int out_size) {
    const float* h   = (const float*)d_in[0];
    const float* e   = (const float*)d_in[1];
    const int*   src = (const int*)d_in[2];
    const int*   dst = (const int*)d_in[3];
    const float* eps = (const float*)d_in[4];
    const float* W1  = (const float*)d_in[5];
    const float* b1  = (const float*)d_in[6];
    const float* W2  = (const float*)d_in[7];
    const float* b2  = (const float*)d_in[8];
    const float* gh  = (const float*)d_in[9];
    const float* bh  = (const float*)d_in[10];
    const float* ge  = (const float*)d_in[11];
    const float* be  = (const float*)d_in[12];

    int N = in_sizes[0] / D;
    int E = in_sizes[1] / D;
    float* out_h = (float*)d_out;
    float* out_e = out_h + (size_t)N * D;

    cudaFuncSetAttribute(mlp_kernel, cudaFuncAttributeMaxDynamicSharedMemorySize, SMEM_BYTES);

    zero_kernel<<<1024, 256>>>();
    scatter_kernel<<<(E * 16 + 255) / 256, 256>>>(h, src, dst, E);

    int nblk = (N + TILE_M - 1) / TILE_M;
    int eblk = (E + TILE_M - 1) / TILE_M;
    mlp_kernel<<<nblk, NTHREADS, SMEM_BYTES>>>(h, eps, W1, b1, W2, b2, out_h, N, 0);
    mlp_kernel<<<eblk, NTHREADS, SMEM_BYTES>>>(e, eps, W1, b1, W2, b2, out_e, E, 1);

    stats_kernel<<<1, 128>>>(N, E);

    apply_kernel<<<(N * 16 + 255) / 256, 256>>>(h, gh, bh, out_h, N, 0);
    apply_kernel<<<(E * 16 + 255) / 256, 256>>>(e, ge, be, out_e, E, 1);
}

// round 4
// speedup vs baseline: 1.0400x; 1.0400x over previous
#include <cuda_runtime.h>
#include <cuda_bf16.h>

#define D 64
#define TILE_M 64
#define NTHREADS 256
#define NREP 64
#define MAX_N 100000
#define KC 16              // 16 chunks of 4 k-values

// ---------------- scratch (device globals; no allocations allowed) ----------------
__device__ float g_neigh[MAX_N * D];
__device__ float g_sum[2][NREP][D];
__device__ float g_sq[2][NREP][D];
__device__ __align__(16) float g_mean[2][D];
__device__ __align__(16) float g_rstd[2][D];
__device__ float4 g_W1t[KC * D];   // [kc][c] -> W[4kc..4kc+3][c]
__device__ float4 g_W2t[KC * D];

// ---------------- packed fp32x2 helpers ----------------
__device__ __forceinline__ void unpack2(unsigned long long v, float& lo, float& hi) {
    asm("mov.b64 {%0, %1}, %2;" : "=f"(lo), "=f"(hi) : "l"(v));
}
__device__ __forceinline__ unsigned long long fma2(unsigned long long a,
                                                   unsigned long long b,
                                                   unsigned long long c) {
    unsigned long long d;
    asm("fma.rn.f32x2 %0, %1, %2, %3;" : "=l"(d) : "l"(a), "l"(b), "l"(c));
    return d;
}

// ---------------- K0: zero scratch + build k-blocked W transpose ----------------
__global__ void zero_kernel(const float* __restrict__ W1, const float* __restrict__ W2) {
    int tid = blockIdx.x * blockDim.x + threadIdx.x;
    int stride = gridDim.x * blockDim.x;
    float4* p = (float4*)g_neigh;
    const int n4 = MAX_N * D / 4;
    for (int i = tid; i < n4; i += stride) p[i] = make_float4(0.f, 0.f, 0.f, 0.f);
    float* s = &g_sum[0][0][0];
    float* q = &g_sq[0][0][0];
    const int ns = 2 * NREP * D;
    for (int i = tid; i < ns; i += stride) { s[i] = 0.f; q[i] = 0.f; }
    // W transpose into k-blocked float4 chunks
    for (int i = tid; i < 2 * KC * D; i += stride) {
        int m = i >> 10;          // 0 = W1, 1 = W2
        int idx = i & 1023;
        int kc = idx >> 6;
        int c = idx & 63;
        const float* W = m ? W2 : W1;
        float4 v = make_float4(__ldg(&W[(4 * kc + 0) * D + c]),
                               __ldg(&W[(4 * kc + 1) * D + c]),
                               __ldg(&W[(4 * kc + 2) * D + c]),
                               __ldg(&W[(4 * kc + 3) * D + c]));
        if (m) g_W2t[idx] = v; else g_W1t[idx] = v;
    }
}

// ---------------- K1: scatter-sum  neigh[dst] += h[src]  ----------------
__global__ void scatter_kernel(const float* __restrict__ h,
                               const int* __restrict__ src,
                               const int* __restrict__ dst, int E) {
    int idx = blockIdx.x * blockDim.x + threadIdx.x;
    int total = E * 16;
    if (idx >= total) return;
    int e = idx >> 4;
    int c = idx & 15;
    int s = __ldg(&src[e]);
    int d = __ldg(&dst[e]);
    float4 v = __ldg((const float4*)(h + (size_t)s * D) + c);
    float* p = g_neigh + (size_t)d * D + c * 4;
    asm volatile("red.global.add.v4.f32 [%0], {%1, %2, %3, %4};"
                 :: "l"(p), "f"(v.x), "f"(v.y), "f"(v.z), "f"(v.w) : "memory");
}

// smem: stage float4[KC*64] (16KB) + Ws ulonglong2[2][KC*64] (32KB) + stats (512B)
#define STAGE_N (KC * 64)
#define SMEM_BYTES (STAGE_N * 16 + 2 * STAGE_N * 16 + 512)

// ---------------- K2/K3: fused MLP (+ column stats) ----------------
__global__ __launch_bounds__(NTHREADS, 2)
void mlp_kernel(const float* __restrict__ xin,
                const float* __restrict__ epsp,
                const float* __restrict__ b1, const float* __restrict__ b2,
                float* __restrict__ out, int M, int target) {
    extern __shared__ char smem_raw[];
    float4* stage = (float4*)smem_raw;
    ulonglong2* Ws = (ulonglong2*)(smem_raw + STAGE_N * 16);   // [layer*1024 + idx]
    float* sstat = (float*)(smem_raw + STAGE_N * 16 + 2 * STAGE_N * 16);
    float* ssq = sstat + 64;

    int tid = threadIdx.x;
    int row0 = blockIdx.x * TILE_M;

    // copy k-blocked transposed weights to smem
    for (int i = tid; i < STAGE_N; i += NTHREADS) {
        Ws[i] = *(const ulonglong2*)&g_W1t[i];
        Ws[STAGE_N + i] = *(const ulonglong2*)&g_W2t[i];
    }
    if (tid < 64) { sstat[tid] = 0.f; ssq[tid] = 0.f; }

    // fill stage: [kc][r ^ (kc&7)] <- x[row0+r][4kc..4kc+3]
    float epsv = 1.f;
    if (target == 0) epsv = 1.f + __ldg(&epsp[0]);
    for (int ch = tid; ch < TILE_M * KC; ch += NTHREADS) {
        int kc = ch & 15;
        int r = ch >> 4;
        int gr = row0 + r;
        float4 v = make_float4(0.f, 0.f, 0.f, 0.f);
        if (gr < M) {
            if (target == 0) {
                float4 a = __ldg((const float4*)(xin + (size_t)gr * D) + kc);
                float4 n = *((const float4*)(g_neigh + (size_t)gr * D) + kc);
                v.x = fmaf(epsv, a.x, n.x);
                v.y = fmaf(epsv, a.y, n.y);
                v.z = fmaf(epsv, a.z, n.z);
                v.w = fmaf(epsv, a.w, n.w);
            } else {
                v = __ldg((const float4*)(xin + (size_t)gr * D) + kc);
            }
        }
        stage[kc * 64 + (r ^ (kc & 7))] = v;
    }
    __syncthreads();

    int w = tid >> 5;
    int lane = tid & 31;
    int rg = ((w & 1) << 3) | (lane & 7);      // 0..15
    int cg = ((w >> 1) << 2) | (lane >> 3);    // 0..15
    int c0 = cg * 4;
    const ulonglong2* stU = (const ulonglong2*)stage;

    unsigned long long acc[4][4];

    // ---- layer 1 ----
#pragma unroll
    for (int i = 0; i < 4; ++i)
#pragma unroll
        for (int j = 0; j < 4; ++j) acc[i][j] = 0ull;

#pragma unroll
    for (int kc = 0; kc < KC; ++kc) {
        int sw = kc & 7;
        ulonglong2 xv[4], wv[4];
#pragma unroll
        for (int i = 0; i < 4; ++i) xv[i] = stU[kc * 64 + ((rg + 16 * i) ^ sw)];
#pragma unroll
        for (int j = 0; j < 4; ++j) wv[j] = Ws[kc * 64 + c0 + j];
#pragma unroll
        for (int i = 0; i < 4; ++i)
#pragma unroll
            for (int j = 0; j < 4; ++j) {
                acc[i][j] = fma2(xv[i].x, wv[j].x, acc[i][j]);
                acc[i][j] = fma2(xv[i].y, wv[j].y, acc[i][j]);
            }
    }
    __syncthreads();   // all layer-1 reads of stage done

    // ---- transition: t = relu(lo+hi+b1), write back in k-blocked layout ----
    {
        float bb[4];
#pragma unroll
        for (int j = 0; j < 4; ++j) bb[j] = __ldg(&b1[c0 + j]);
#pragma unroll
        for (int i = 0; i < 4; ++i) {
            int r = rg + 16 * i;
            float t[4];
#pragma unroll
            for (int j = 0; j < 4; ++j) {
                float lo, hi;
                unpack2(acc[i][j], lo, hi);
                t[j] = fmaxf(lo + hi + bb[j], 0.f);
            }
            stage[cg * 64 + (r ^ (cg & 7))] = make_float4(t[0], t[1], t[2], t[3]);
        }
    }
    __syncthreads();

    // ---- layer 2 ----
#pragma unroll
    for (int i = 0; i < 4; ++i)
#pragma unroll
        for (int j = 0; j < 4; ++j) acc[i][j] = 0ull;

#pragma unroll
    for (int kc = 0; kc < KC; ++kc) {
        int sw = kc & 7;
        ulonglong2 xv[4], wv[4];
#pragma unroll
        for (int i = 0; i < 4; ++i) xv[i] = stU[kc * 64 + ((rg + 16 * i) ^ sw)];
#pragma unroll
        for (int j = 0; j < 4; ++j) wv[j] = Ws[STAGE_N + kc * 64 + c0 + j];
#pragma unroll
        for (int i = 0; i < 4; ++i)
#pragma unroll
            for (int j = 0; j < 4; ++j) {
                acc[i][j] = fma2(xv[i].x, wv[j].x, acc[i][j]);
                acc[i][j] = fma2(xv[i].y, wv[j].y, acc[i][j]);
            }
    }

    // ---- epilogue: y = lo+hi+b2, store pre-norm, accumulate column stats ----
    float bb[4];
#pragma unroll
    for (int j = 0; j < 4; ++j) bb[j] = __ldg(&b2[c0 + j]);
    float cs[4] = {0.f, 0.f, 0.f, 0.f};
    float cq[4] = {0.f, 0.f, 0.f, 0.f};
#pragma unroll
    for (int i = 0; i < 4; ++i) {
        int gr = row0 + rg + 16 * i;
        float y[4];
#pragma unroll
        for (int j = 0; j < 4; ++j) {
            float lo, hi;
            unpack2(acc[i][j], lo, hi);
            y[j] = lo + hi + bb[j];
        }
        if (gr < M) {
            *(float4*)(out + (size_t)gr * D + c0) = make_float4(y[0], y[1], y[2], y[3]);
#pragma unroll
            for (int j = 0; j < 4; ++j) { cs[j] += y[j]; cq[j] += y[j] * y[j]; }
        }
    }
#pragma unroll
    for (int j = 0; j < 4; ++j) {
        atomicAdd(&sstat[c0 + j], cs[j]);
        atomicAdd(&ssq[c0 + j], cq[j]);
    }
    __syncthreads();
    if (tid < 64) {
        int rep = blockIdx.x & (NREP - 1);
        atomicAdd(&g_sum[target][rep][tid], sstat[tid]);
        atomicAdd(&g_sq[target][rep][tid], ssq[tid]);
    }
}

// ---------------- K4: finalize mean / rstd ----------------
__global__ void stats_kernel(int N, int E) {
    int t = threadIdx.x;          // 128 threads
    int target = t >> 6;
    int c = t & 63;
    float s = 0.f, q = 0.f;
#pragma unroll
    for (int r = 0; r < NREP; ++r) { s += g_sum[target][r][c]; q += g_sq[target][r][c]; }
    float cnt = target ? (float)E : (float)N;
    float m = s / cnt;
    float var = q / cnt - m * m;
    g_mean[target][c] = m;
    g_rstd[target][c] = rsqrtf(var + 1e-5f);
}

// ---------------- K5/K6: normalize + relu + residual (in place on d_out) ----------------
__global__ void apply_kernel(const float* __restrict__ res,
                             const float* __restrict__ gamma,
                             const float* __restrict__ beta,
                             float* __restrict__ y, int M, int target) {
    int idx = blockIdx.x * blockDim.x + threadIdx.x;
    int total = M * 16;
    if (idx >= total) return;
    int r = idx >> 4;
    int c4 = idx & 15;
    size_t off = (size_t)r * D + c4 * 4;
    float4 v = *(float4*)(y + off);
    float4 rs = __ldg((const float4*)res + (off >> 2));
    float4 g = __ldg((const float4*)gamma + c4);
    float4 b = __ldg((const float4*)beta + c4);
    int c = c4 * 4;
    float4 m = *(const float4*)&g_mean[target][c];
    float4 sd = *(const float4*)&g_rstd[target][c];
    float4 o;
    o.x = rs.x + fmaxf(g.x * (v.x - m.x) * sd.x + b.x, 0.f);
    o.y = rs.y + fmaxf(g.y * (v.y - m.y) * sd.y + b.y, 0.f);
    o.z = rs.z + fmaxf(g.z * (v.z - m.z) * sd.z + b.z, 0.f);
    o.w = rs.w + fmaxf(g.w * (v.w - m.w) * sd.w + b.w, 0.f);
    *(float4*)(y + off) = o;
}

// ---------------- launcher ----------------
extern "C" void kernel_launch(void* const* d_in, const int* in_sizes, int n_in,
                              void* d_out, int out_size) {
    const float* h   = (const float*)d_in[0];
    const float* e   = (const float*)d_in[1];
    const int*   src = (const int*)d_in[2];
    const int*   dst = (const int*)d_in[3];
    const float* eps = (const float*)d_in[4];
    const float* W1  = (const float*)d_in[5];
    const float* b1  = (const float*)d_in[6];
    const float* W2  = (const float*)d_in[7];
    const float* b2  = (const float*)d_in[8];
    const float* gh  = (const float*)d_in[9];
    const float* bh  = (const float*)d_in[10];
    const float* ge  = (const float*)d_in[11];
    const float* be  = (const float*)d_in[12];

    int N = in_sizes[0] / D;
    int E = in_sizes[1] / D;
    float* out_h = (float*)d_out;
    float* out_e = out_h + (size_t)N * D;

    cudaFuncSetAttribute(mlp_kernel, cudaFuncAttributeMaxDynamicSharedMemorySize, SMEM_BYTES);

    zero_kernel<<<1024, 256>>>(W1, W2);
    scatter_kernel<<<(E * 16 + 255) / 256, 256>>>(h, src, dst, E);

    int nblk = (N + TILE_M - 1) / TILE_M;
    int eblk = (E + TILE_M - 1) / TILE_M;
    mlp_kernel<<<nblk, NTHREADS, SMEM_BYTES>>>(h, eps, b1, b2, out_h, N, 0);
    mlp_kernel<<<eblk, NTHREADS, SMEM_BYTES>>>(e, eps, b1, b2, out_e, E, 1);

    stats_kernel<<<1, 128>>>(N, E);

    apply_kernel<<<(N * 16 + 255) / 256, 256>>>(h, gh, bh, out_h, N, 0);
    apply_kernel<<<(E * 16 + 255) / 256, 256>>>(e, ge, be, out_e, E, 1);
}